// round 1
// baseline (speedup 1.0000x reference)
#include <cuda_runtime.h>
#include <cstdint>

#define BB 4
#define FF 3
#define NPTS 8192
#define DD 16
#define KNN_K 32
#define OO 64
#define ALPHA 0.2f

// Scratch (device globals -- no allocations allowed)
__device__ float g_y1[BB * NPTS * OO];          // 8 MB: W1 . x[:,m]   layout [b][m][o]
__device__ float g_c [BB * NPTS * OO];          // 8 MB: (W2-W1).x[:,n] layout [b][n][o]
__device__ int   g_idx[BB * NPTS * KNN_K];      // 4 MB: knn indices

// ---------------------------------------------------------------------------
// Kernel 1: per-point feature projections.
//   y1[b][n][o] = sum_d W[o][d]      * x[b][d][n]
//   c [b][n][o] = sum_d W[o][D+d]    * x[b][d][n]  -  y1
// ---------------------------------------------------------------------------
__global__ __launch_bounds__(256) void precompute_kernel(
    const float* __restrict__ x, const float* __restrict__ W)
{
    __shared__ float sW[OO * 2 * DD];
    int tid = threadIdx.x;
    for (int i = tid; i < OO * 2 * DD; i += blockDim.x) sW[i] = W[i];
    __syncthreads();

    int gid = blockIdx.x * blockDim.x + tid;    // over B*N
    int b = gid / NPTS, n = gid % NPTS;

    float xv[DD];
#pragma unroll
    for (int d = 0; d < DD; d++) xv[d] = x[(b * DD + d) * NPTS + n];

    float* y1p = &g_y1[(b * NPTS + n) * OO];
    float* cp  = &g_c [(b * NPTS + n) * OO];
#pragma unroll 4
    for (int o = 0; o < OO; o++) {
        float s1 = 0.f, s2 = 0.f;
#pragma unroll
        for (int d = 0; d < DD; d++) {
            s1 = __fmaf_rn(sW[o * 2 * DD + d],      xv[d], s1);
            s2 = __fmaf_rn(sW[o * 2 * DD + DD + d], xv[d], s2);
        }
        y1p[o] = s1;
        cp[o]  = s2 - s1;
    }
}

// ---------------------------------------------------------------------------
// Kernel 2: brute-force 32-NN, thread-per-query, candidates broadcast from smem.
// Distance arithmetic mirrors the reference exactly:
//   xx[m]   = fl(fl(fl(p0*p0)+fl(p1*p1))+fl(p2*p2))     (no fma)
//   negd    = fl(fl(2*s - xx[n]) - xx[m]),  s = fma chain over f
// Selection: 32 smallest keys, key = <ordered-bits(-negd), m>  (stable ties).
// Top-32 buffer: 4 groups of 8 u64 keys in registers + group maxima.
// ---------------------------------------------------------------------------
__global__ __launch_bounds__(256) void knn_kernel(const float* __restrict__ points)
{
    extern __shared__ float sm[];
    float* sp0 = sm;
    float* sp1 = sm + NPTS;
    float* sp2 = sm + 2 * NPTS;
    float* sxx = sm + 3 * NPTS;

    int b = blockIdx.y;
    int tid = threadIdx.x;
    const float* pb = points + b * FF * NPTS;

    for (int m = tid; m < NPTS; m += blockDim.x) {
        float a0 = pb[m], a1 = pb[NPTS + m], a2 = pb[2 * NPTS + m];
        sp0[m] = a0; sp1[m] = a1; sp2[m] = a2;
        sxx[m] = __fadd_rn(__fadd_rn(__fmul_rn(a0, a0), __fmul_rn(a1, a1)),
                           __fmul_rn(a2, a2));
    }
    __syncthreads();

    int n = blockIdx.x * blockDim.x + tid;
    float q0 = sp0[n], q1 = sp1[n], q2 = sp2[n], xxn = sxx[n];

    unsigned long long keyv[KNN_K];
    unsigned long long gmax[4];
#pragma unroll
    for (int j = 0; j < KNN_K; j++) keyv[j] = 0xFFFFFFFF00000000ULL | (unsigned)j;
#pragma unroll
    for (int g = 0; g < 4; g++) gmax[g] = 0xFFFFFFFF00000000ULL | (unsigned)(g * 8 + 7);
    unsigned long long curMax = 0xFFFFFFFF0000001FULL;

#pragma unroll 2
    for (int m = 0; m < NPTS; m++) {
        float s = __fmul_rn(q0, sp0[m]);
        s = __fmaf_rn(q1, sp1[m], s);
        s = __fmaf_rn(q2, sp2[m], s);
        float negd = __fsub_rn(__fsub_rn(__fmul_rn(2.0f, s), xxn), sxx[m]);
        float dpos = -negd;                           // exact negation: same order
        unsigned ub = __float_as_uint(dpos);
        unsigned mapped = ub ^ (((unsigned)((int)ub >> 31)) | 0x80000000u);
        unsigned long long key = ((unsigned long long)mapped << 32) | (unsigned)m;

        if (key < curMax) {
            // exactly one group owns curMax (keys unique)
#pragma unroll
            for (int g = 0; g < 4; g++) {
                if (gmax[g] == curMax) {
#pragma unroll
                    for (int j = 0; j < 8; j++)
                        if (keyv[g * 8 + j] == curMax) keyv[g * 8 + j] = key;
                    unsigned long long mx = keyv[g * 8];
#pragma unroll
                    for (int j = 1; j < 8; j++) {
                        unsigned long long v = keyv[g * 8 + j];
                        mx = (v > mx) ? v : mx;
                    }
                    gmax[g] = mx;
                }
            }
            unsigned long long a = (gmax[0] > gmax[1]) ? gmax[0] : gmax[1];
            unsigned long long c2 = (gmax[2] > gmax[3]) ? gmax[2] : gmax[3];
            curMax = (a > c2) ? a : c2;
        }
    }

    int* op = &g_idx[(b * NPTS + n) * KNN_K];
#pragma unroll
    for (int j = 0; j < KNN_K; j++) op[j] = (int)(keyv[j] & 0xFFFFFFFFu);
}

// ---------------------------------------------------------------------------
// Kernel 3: out[b][o][n] = (1/K) * sum_k leaky( y1[b][idx[n][k]][o] + c[b][n][o] )
// Block handles one (b, 32-wide n tile); threads = 64 o-lanes x 4 n-subs.
// Gathers are o-contiguous (coalesced 256B rows, L2-resident); output staged
// through smem for coalesced n-contiguous stores.
// ---------------------------------------------------------------------------
__global__ __launch_bounds__(256) void edgeconv_kernel(float* __restrict__ out)
{
    __shared__ float stile[OO][33];       // pad: conflict-free col writes
    __shared__ int   sidx[32 * KNN_K];

    int b = blockIdx.y;
    int nbase = blockIdx.x * 32;
    int tid = threadIdx.x;

    for (int i = tid; i < 32 * KNN_K; i += 256)
        sidx[i] = g_idx[(b * NPTS + nbase) * KNN_K + i];
    __syncthreads();

    int o = tid & 63;
    int sub = tid >> 6;                   // 0..3

    for (int nt = 0; nt < 8; nt++) {
        int nl = nt * 4 + sub;            // local n 0..31
        int n = nbase + nl;
        float c = g_c[(b * NPTS + n) * OO + o];
        float acc = 0.f;
        const int* ip = &sidx[nl * KNN_K];
#pragma unroll 4
        for (int k = 0; k < KNN_K; k++) {
            int m = ip[k];
            float t = g_y1[(b * NPTS + m) * OO + o] + c;
            acc += (t >= 0.f) ? t : ALPHA * t;
        }
        stile[o][nl] = acc * (1.0f / KNN_K);
    }
    __syncthreads();

#pragma unroll
    for (int r = 0; r < 8; r++) {
        int oo = r * 8 + (tid >> 5);
        int nn = tid & 31;
        out[(b * OO + oo) * NPTS + nbase + nn] = stile[oo][nn];
    }
}

// ---------------------------------------------------------------------------
extern "C" void kernel_launch(void* const* d_in, const int* in_sizes, int n_in,
                              void* d_out, int out_size)
{
    const float* points = nullptr;
    const float* x = nullptr;
    const float* W = nullptr;
    for (int i = 0; i < n_in; i++) {
        if      (in_sizes[i] == BB * FF * NPTS) points = (const float*)d_in[i];
        else if (in_sizes[i] == BB * DD * NPTS) x      = (const float*)d_in[i];
        else if (in_sizes[i] == OO * 2 * DD)    W      = (const float*)d_in[i];
    }
    float* out = (float*)d_out;

    precompute_kernel<<<(BB * NPTS) / 256, 256>>>(x, W);

    size_t smem = (size_t)4 * NPTS * sizeof(float);   // 128 KB
    cudaFuncSetAttribute(knn_kernel, cudaFuncAttributeMaxDynamicSharedMemorySize,
                         (int)smem);
    knn_kernel<<<dim3(NPTS / 256, BB), 256, smem>>>(points);

    edgeconv_kernel<<<dim3(NPTS / 32, BB), 256>>>(out);
}

// round 3
// speedup vs baseline: 2.8462x; 2.8462x over previous
#include <cuda_runtime.h>
#include <cstdint>

#define BB 4
#define FF 3
#define NPTS 8192
#define DD 16
#define KNN_K 32
#define OO 64
#define ALPHA 0.2f
#define TILE 2048
#define WARPS_PER_BLK 16

// Scratch (device globals -- no allocations allowed)
__device__ float g_y1[BB * NPTS * OO];          // 8 MB: W1 . x[:,m]   layout [b][m][o]
__device__ float g_c [BB * NPTS * OO];          // 8 MB: (W2-W1).x[:,n] layout [b][n][o]
__device__ int   g_idx[BB * NPTS * KNN_K];      // 4 MB: knn indices

// ---------------------------------------------------------------------------
// Kernel 1: per-point feature projections.
//   y1[b][n][o] = sum_d W[o][d]   * x[b][d][n]
//   c [b][n][o] = sum_d W[o][D+d] * x[b][d][n]  -  y1
// ---------------------------------------------------------------------------
__global__ __launch_bounds__(256) void precompute_kernel(
    const float* __restrict__ x, const float* __restrict__ W)
{
    __shared__ float sW[OO * 2 * DD];
    int tid = threadIdx.x;
    for (int i = tid; i < OO * 2 * DD; i += blockDim.x) sW[i] = W[i];
    __syncthreads();

    int gid = blockIdx.x * blockDim.x + tid;    // over B*N
    int b = gid / NPTS, n = gid % NPTS;

    float xv[DD];
#pragma unroll
    for (int d = 0; d < DD; d++) xv[d] = x[(b * DD + d) * NPTS + n];

    float* y1p = &g_y1[(b * NPTS + n) * OO];
    float* cp  = &g_c [(b * NPTS + n) * OO];
#pragma unroll 4
    for (int o = 0; o < OO; o++) {
        float s1 = 0.f, s2 = 0.f;
#pragma unroll
        for (int d = 0; d < DD; d++) {
            s1 = __fmaf_rn(sW[o * 2 * DD + d],      xv[d], s1);
            s2 = __fmaf_rn(sW[o * 2 * DD + DD + d], xv[d], s2);
        }
        y1p[o] = s1;
        cp[o]  = s2 - s1;
    }
}

// ---------------------------------------------------------------------------
// Kernel 2: brute-force 32-NN, WARP-PER-QUERY.
// Distance arithmetic identical to the verified R1 kernel:
//   xx[m] = fl(fl(fl(p0*p0)+fl(p1*p1))+fl(p2*p2))   (no fma)
//   negd  = fl(fl(2*s - xx[n]) - xx[m]),  s = mul+fma chain over f
//   key   = <ordered-bits(-negd), m>  (unique; stable ties like lax.top_k)
// Top-32 kept SORTED across lanes (lane L = L-th smallest). Insertion is a
// warp-cooperative shfl_up shift (~10 warp-inst), no per-thread scans.
// The insert loop is warp-converged: pass/bk/worst are all warp-uniform.
// ---------------------------------------------------------------------------
__global__ __launch_bounds__(32 * WARPS_PER_BLK) void knn_kernel(
    const float* __restrict__ points)
{
    __shared__ float4 scand[TILE];

    const unsigned FULL = 0xFFFFFFFFu;
    int b = blockIdx.y;
    const float* pb = points + b * FF * NPTS;
    int tid  = threadIdx.x;
    int wid  = tid >> 5;
    int lane = tid & 31;
    int n = blockIdx.x * WARPS_PER_BLK + wid;      // this warp's query

    float q0 = pb[n], q1 = pb[NPTS + n], q2 = pb[2 * NPTS + n];
    float xxn = __fadd_rn(__fadd_rn(__fmul_rn(q0, q0), __fmul_rn(q1, q1)),
                          __fmul_rn(q2, q2));

    // sorted top-32, one key per lane; init keys larger than any real key
    unsigned long long listk = 0xFFFFFFFF00000000ULL | (unsigned)lane;
    unsigned long long worst = 0xFFFFFFFF0000001FULL;   // lane 31's key

    for (int t = 0; t < NPTS; t += TILE) {
        __syncthreads();
        // cooperative tile load: candidate coords + exact xx
        for (int i = tid; i < TILE; i += 32 * WARPS_PER_BLK) {
            int m = t + i;
            float a0 = pb[m], a1 = pb[NPTS + m], a2 = pb[2 * NPTS + m];
            float xx = __fadd_rn(__fadd_rn(__fmul_rn(a0, a0), __fmul_rn(a1, a1)),
                                 __fmul_rn(a2, a2));
            scand[i] = make_float4(a0, a1, a2, xx);
        }
        __syncthreads();

#pragma unroll 2
        for (int s = 0; s < TILE; s += 32) {
            int i = s + lane;
            float4 c = scand[i];
            float ss = __fmul_rn(q0, c.x);
            ss = __fmaf_rn(q1, c.y, ss);
            ss = __fmaf_rn(q2, c.z, ss);
            float negd = __fsub_rn(__fsub_rn(__fmul_rn(2.0f, ss), xxn), c.w);
            float dpos = -negd;
            unsigned ub = __float_as_uint(dpos);
            unsigned mapped = ub ^ (((unsigned)((int)ub >> 31)) | 0x80000000u);
            unsigned long long key =
                ((unsigned long long)mapped << 32) | (unsigned)(t + i);

            unsigned pass = __ballot_sync(FULL, key < worst);
            while (pass) {                      // warp-uniform loop
                int src = __ffs(pass) - 1;
                pass &= pass - 1;
                unsigned long long bk = __shfl_sync(FULL, key, src);
                if (bk < worst) {               // uniform branch
                    unsigned long long up = __shfl_up_sync(FULL, listk, 1);
                    bool gt   = listk > bk;
                    bool upgt = (lane > 0) && (up > bk);
                    if (gt) listk = upgt ? up : bk;
                    worst = __shfl_sync(FULL, listk, 31);
                }
            }
        }
    }

    // lane L holds L-th nearest (ascending dist, stable idx ties)
    g_idx[(b * NPTS + n) * KNN_K + lane] = (int)(listk & 0xFFFFFFFFu);
}

// ---------------------------------------------------------------------------
// Kernel 3: out[b][o][n] = (1/K) * sum_k leaky( y1[b][idx[n][k]][o] + c[b][n][o] )
// ---------------------------------------------------------------------------
__global__ __launch_bounds__(256) void edgeconv_kernel(float* __restrict__ out)
{
    __shared__ float stile[OO][33];
    __shared__ int   sidx[32 * KNN_K];

    int b = blockIdx.y;
    int nbase = blockIdx.x * 32;
    int tid = threadIdx.x;

    for (int i = tid; i < 32 * KNN_K; i += 256)
        sidx[i] = g_idx[(b * NPTS + nbase) * KNN_K + i];
    __syncthreads();

    int o = tid & 63;
    int sub = tid >> 6;

    for (int nt = 0; nt < 8; nt++) {
        int nl = nt * 4 + sub;
        int n = nbase + nl;
        float c = g_c[(b * NPTS + n) * OO + o];
        float acc = 0.f;
        const int* ip = &sidx[nl * KNN_K];
#pragma unroll 4
        for (int k = 0; k < KNN_K; k++) {
            int m = ip[k];
            float t = g_y1[(b * NPTS + m) * OO + o] + c;
            acc += (t >= 0.f) ? t : ALPHA * t;
        }
        stile[o][nl] = acc * (1.0f / KNN_K);
    }
    __syncthreads();

#pragma unroll
    for (int r = 0; r < 8; r++) {
        int oo = r * 8 + (tid >> 5);
        int nn = tid & 31;
        out[(b * OO + oo) * NPTS + nbase + nn] = stile[oo][nn];
    }
}

// ---------------------------------------------------------------------------
extern "C" void kernel_launch(void* const* d_in, const int* in_sizes, int n_in,
                              void* d_out, int out_size)
{
    const float* points = nullptr;
    const float* x = nullptr;
    const float* W = nullptr;
    for (int i = 0; i < n_in; i++) {
        if      (in_sizes[i] == BB * FF * NPTS) points = (const float*)d_in[i];
        else if (in_sizes[i] == BB * DD * NPTS) x      = (const float*)d_in[i];
        else if (in_sizes[i] == OO * 2 * DD)    W      = (const float*)d_in[i];
    }
    float* out = (float*)d_out;

    precompute_kernel<<<(BB * NPTS) / 256, 256>>>(x, W);

    knn_kernel<<<dim3(NPTS / WARPS_PER_BLK, BB), 32 * WARPS_PER_BLK>>>(points);

    edgeconv_kernel<<<dim3(NPTS / 32, BB), 256>>>(out);
}